// round 9
// baseline (speedup 1.0000x reference)
#include <cuda_runtime.h>
#include <cstdint>

#define T_LEN 8192
#define NTHREADS 256
#define NWARPS 8

__device__ __forceinline__ uint32_t rotl32(uint32_t x, int r) {
    return (x << r) | (x >> (32 - r));
}

// Threefry-2x32, 20 rounds, key = (0,42); returns x0^x1 (JAX partitionable fold).
__device__ __forceinline__ uint32_t threefry_xor(uint32_t c0, uint32_t c1) {
    const uint32_t ks0 = 0u, ks1 = 42u;
    const uint32_t ks2 = ks0 ^ ks1 ^ 0x1BD11BDAu;
    uint32_t x0 = c0 + ks0, x1 = c1 + ks1;
#define TF_R4(a,b,c,d) \
    x0 += x1; x1 = rotl32(x1,a); x1 ^= x0; \
    x0 += x1; x1 = rotl32(x1,b); x1 ^= x0; \
    x0 += x1; x1 = rotl32(x1,c); x1 ^= x0; \
    x0 += x1; x1 = rotl32(x1,d); x1 ^= x0;
    TF_R4(13,15,26,6);   x0 += ks1; x1 += ks2 + 1u;
    TF_R4(17,29,16,24);  x0 += ks2; x1 += ks0 + 2u;
    TF_R4(13,15,26,6);   x0 += ks0; x1 += ks1 + 3u;
    TF_R4(17,29,16,24);  x0 += ks1; x1 += ks2 + 4u;
    TF_R4(13,15,26,6);   x0 += ks2; x1 += ks0 + 5u;
#undef TF_R4
    return x0 ^ x1;
}

__global__ __launch_bounds__(NTHREADS)
void midi_stats_mlp_kernel(const int* __restrict__ tokens,
                           const float* __restrict__ W1,
                           const float* __restrict__ b1,
                           const float* __restrict__ W2,
                           const float* __restrict__ b2,
                           float* __restrict__ out) {
    // Per-THREAD private byte histograms: counter(t, b) at word
    // (b>>2)*NTHREADS + t, byte (b&3). Bank = t%32 = lane -> conflict-free;
    // each thread touches only its own bytes -> no atomics, plain LDS/STS.
    __shared__ uint32_t priv[32 * NTHREADS];        // 32 KB
    __shared__ uint32_t plo[NWARPS][32], phi[NWARPS][32];
    __shared__ unsigned s_sum, s_ssq;
    __shared__ float stats[152];
    __shared__ float h[256];

    const int b   = blockIdx.x;
    const int tid = threadIdx.x;
    const int wid = tid >> 5;
    const uint32_t lane = tid & 31u;

    // Zero private histogram (32 words per thread, bank=lane, conflict-free)
#pragma unroll
    for (int w = 0; w < 32; w++) priv[w * NTHREADS + tid] = 0u;
    if (tid == 0) { s_sum = 0u; s_ssq = 0u; }
    __syncthreads();

    // ---- Hot loop: 32 tokens/thread, byte-RMW histogram + moments ----
    const int4* tp = reinterpret_cast<const int4*>(tokens + (size_t)b * T_LEN);
    unsigned char* mybase = reinterpret_cast<unsigned char*>(priv) + tid * 4;
    unsigned lsum = 0, lssq = 0;
#pragma unroll
    for (int i = 0; i < T_LEN / 4 / NTHREADS; i++) {   // 8 iterations
        int4 v = tp[i * NTHREADS + tid];
        lsum += (unsigned)(v.x + v.y) + (unsigned)(v.z + v.w);
        lssq += (unsigned)(v.x * v.x) + (unsigned)(v.y * v.y)
              + (unsigned)(v.z * v.z) + (unsigned)(v.w * v.w);
        // byte offset for bin = t*4 + ((v & 124) << 7) + (v & 3)   [NTHREADS=256 -> <<7 stays? no:]
        // word stride is NTHREADS words: ((v>>2) * NTHREADS + t)*4 + (v&3)
        mybase[(((unsigned)v.x & 124u) << 8) + ((unsigned)v.x & 3u)]++;
        mybase[(((unsigned)v.y & 124u) << 8) + ((unsigned)v.y & 3u)]++;
        mybase[(((unsigned)v.z & 124u) << 8) + ((unsigned)v.z & 3u)]++;
        mybase[(((unsigned)v.w & 124u) << 8) + ((unsigned)v.w & 3u)]++;
    }
    // moments: warp reduce + 1 atomic per warp
    lsum = __reduce_add_sync(0xffffffffu, lsum);
    lssq = __reduce_add_sync(0xffffffffu, lssq);
    if (lane == 0) {
        atomicAdd(&s_sum, lsum);
        atomicAdd(&s_ssq, lssq);
    }
    __syncthreads();

    // ---- Fold stage A: per-warp SIMD-in-word sums over 32 lanes ----
    // word w holds bins {4w..4w+3} as bytes; even/odd bytes -> u16 fields
    // (lane-sum <= 32*32 = 1024, no overflow), REDUX across the warp.
#pragma unroll 8
    for (int w = 0; w < 32; w++) {
        uint32_t x  = priv[w * NTHREADS + tid];       // bank=lane, CF
        uint32_t lo = __reduce_add_sync(0xffffffffu, x & 0x00FF00FFu);
        uint32_t hi = __reduce_add_sync(0xffffffffu, (x >> 8) & 0x00FF00FFu);
        if (lane == 0) { plo[wid][w] = lo; phi[wid][w] = hi; }
    }
    __syncthreads();

    // ---- Fold stage B: combine 8 warp partials; bin tid handled by tid<128 ----
    if (tid < 128) {
        int w = tid >> 2, k = tid & 3;
        int sh = (k >> 1) * 16;
        uint32_t cnt = 0;
#pragma unroll
        for (int q = 0; q < NWARPS; q++) {
            uint32_t p = (k & 1) ? phi[q][w] : plo[q][w];
            cnt += (p >> sh) & 0xFFFFu;                // total <= 8192, fits
        }
        stats[tid] = (float)cnt * (1.0f / 8192.0f);    // f32(8192+1e-8)==8192
    }

    // ---- Remaining stats dims ----
    if (tid == 128) {
        double m = (double)s_sum / 8192.0;
        stats[128] = (float)m;                                                  // mean
        stats[129] = (float)sqrt(((double)s_ssq - (double)s_sum * m) / 8191.0); // unbiased std
    }
    if (tid >= 130 && tid < 138) stats[tid] = 0.0f;
    if (tid >= 138 && tid < 150) {
        // harmony: jax.random.uniform(key(42), (1024,12)), partitionable Threefry
        uint32_t idx = (uint32_t)(b * 12 + (tid - 138));
        uint32_t bits = threefry_xor(0u, idx);
        stats[tid] = __uint_as_float((bits >> 9) | 0x3F800000u) - 1.0f;
    }
    __syncthreads();

    // ---- Layer 1: h = relu(stats @ W1 + b1); 1 column per thread ----
    {
        float acc = b1[tid];
#pragma unroll 10
        for (int s = 0; s < 150; s++)
            acc = fmaf(stats[s], W1[s * 256 + tid], acc);
        h[tid] = fmaxf(acc, 0.0f);
    }
    __syncthreads();

    // ---- Layer 2: out = h @ W2 + b2; first 128 threads ----
    if (tid < 128) {
        float o = b2[tid];
#pragma unroll 8
        for (int k = 0; k < 256; k++)
            o = fmaf(h[k], W2[k * 128 + tid], o);
        out[(size_t)b * 128 + tid] = o;
    }
}

extern "C" void kernel_launch(void* const* d_in, const int* in_sizes, int n_in,
                              void* d_out, int out_size) {
    const int*   tokens = (const int*)d_in[0];
    const float* W1     = (const float*)d_in[1];
    const float* b1     = (const float*)d_in[2];
    const float* W2     = (const float*)d_in[3];
    const float* b2     = (const float*)d_in[4];
    float* out = (float*)d_out;
    midi_stats_mlp_kernel<<<1024, NTHREADS>>>(tokens, W1, b1, W2, b2, out);
}

// round 10
// speedup vs baseline: 1.0009x; 1.0009x over previous
#include <cuda_runtime.h>
#include <cstdint>

#define T_LEN 8192
#define NTHREADS 256
#define NWARPS 8

__device__ __forceinline__ uint32_t rotl32(uint32_t x, int r) {
    return (x << r) | (x >> (32 - r));
}

// Threefry-2x32, 20 rounds, key = (0,42); returns x0^x1 (JAX partitionable fold).
__device__ __forceinline__ uint32_t threefry_xor(uint32_t c0, uint32_t c1) {
    const uint32_t ks0 = 0u, ks1 = 42u;
    const uint32_t ks2 = ks0 ^ ks1 ^ 0x1BD11BDAu;
    uint32_t x0 = c0 + ks0, x1 = c1 + ks1;
#define TF_R4(a,b,c,d) \
    x0 += x1; x1 = rotl32(x1,a); x1 ^= x0; \
    x0 += x1; x1 = rotl32(x1,b); x1 ^= x0; \
    x0 += x1; x1 = rotl32(x1,c); x1 ^= x0; \
    x0 += x1; x1 = rotl32(x1,d); x1 ^= x0;
    TF_R4(13,15,26,6);   x0 += ks1; x1 += ks2 + 1u;
    TF_R4(17,29,16,24);  x0 += ks2; x1 += ks0 + 2u;
    TF_R4(13,15,26,6);   x0 += ks0; x1 += ks1 + 3u;
    TF_R4(17,29,16,24);  x0 += ks1; x1 += ks2 + 4u;
    TF_R4(13,15,26,6);   x0 += ks2; x1 += ks0 + 5u;
#undef TF_R4
    return x0 ^ x1;
}

__device__ __forceinline__ void rmw4(unsigned char* mybase, int4 v,
                                     unsigned& lsum, unsigned& lssq) {
    lsum += (unsigned)(v.x + v.y) + (unsigned)(v.z + v.w);
    lssq += (unsigned)(v.x * v.x) + (unsigned)(v.y * v.y)
          + (unsigned)(v.z * v.z) + (unsigned)(v.w * v.w);
    // byte offset for bin b: word (b>>2)*NTHREADS + t, byte b&3
    //   = t*4 + ((b & 124) << 8) + (b & 3)     [NTHREADS = 256]
    mybase[(((unsigned)v.x & 124u) << 8) + ((unsigned)v.x & 3u)]++;
    mybase[(((unsigned)v.y & 124u) << 8) + ((unsigned)v.y & 3u)]++;
    mybase[(((unsigned)v.z & 124u) << 8) + ((unsigned)v.z & 3u)]++;
    mybase[(((unsigned)v.w & 124u) << 8) + ((unsigned)v.w & 3u)]++;
}

__global__ __launch_bounds__(NTHREADS)
void midi_stats_mlp_kernel(const int* __restrict__ tokens,
                           const float* __restrict__ W1,
                           const float* __restrict__ b1,
                           const float* __restrict__ W2,
                           const float* __restrict__ b2,
                           float* __restrict__ out) {
    // Per-THREAD private byte histograms: no atomics, bank = lane, conflict-free.
    __shared__ uint32_t priv[32 * NTHREADS];        // 32 KB
    __shared__ uint32_t plo[NWARPS][32], phi[NWARPS][32];
    __shared__ unsigned s_sum, s_ssq;
    __shared__ float stats[152];
    __shared__ float h[256];

    const int b   = blockIdx.x;
    const int tid = threadIdx.x;
    const int wid = tid >> 5;
    const uint32_t lane = tid & 31u;

    // ---- FRONT-BATCH all 8 int4 loads (MLP_p1 = 8) before anything else ----
    const int4* tp = reinterpret_cast<const int4*>(tokens + (size_t)b * T_LEN) + tid;
    int4 a0 = tp[0 * NTHREADS];
    int4 a1 = tp[1 * NTHREADS];
    int4 a2 = tp[2 * NTHREADS];
    int4 a3 = tp[3 * NTHREADS];
    int4 a4 = tp[4 * NTHREADS];
    int4 a5 = tp[5 * NTHREADS];
    int4 a6 = tp[6 * NTHREADS];
    int4 a7 = tp[7 * NTHREADS];

    // Zero private histogram while loads are in flight (independent smem work)
#pragma unroll
    for (int w = 0; w < 32; w++) priv[w * NTHREADS + tid] = 0u;
    if (tid == 0) { s_sum = 0u; s_ssq = 0u; }
    __syncthreads();

    // ---- Process 32 tokens: byte-RMW histogram + integer moments ----
    unsigned char* mybase = reinterpret_cast<unsigned char*>(priv) + tid * 4;
    unsigned lsum = 0, lssq = 0;
    rmw4(mybase, a0, lsum, lssq);
    rmw4(mybase, a1, lsum, lssq);
    rmw4(mybase, a2, lsum, lssq);
    rmw4(mybase, a3, lsum, lssq);
    rmw4(mybase, a4, lsum, lssq);
    rmw4(mybase, a5, lsum, lssq);
    rmw4(mybase, a6, lsum, lssq);
    rmw4(mybase, a7, lsum, lssq);

    // moments: warp reduce + 1 atomic per warp
    lsum = __reduce_add_sync(0xffffffffu, lsum);
    lssq = __reduce_add_sync(0xffffffffu, lssq);
    if (lane == 0) {
        atomicAdd(&s_sum, lsum);
        atomicAdd(&s_ssq, lssq);
    }
    __syncthreads();

    // ---- Fold stage A: per-warp SIMD-in-word sums (u16 fields <= 1024) ----
#pragma unroll 8
    for (int w = 0; w < 32; w++) {
        uint32_t x  = priv[w * NTHREADS + tid];       // bank = lane, CF
        uint32_t lo = __reduce_add_sync(0xffffffffu, x & 0x00FF00FFu);
        uint32_t hi = __reduce_add_sync(0xffffffffu, (x >> 8) & 0x00FF00FFu);
        if (lane == 0) { plo[wid][w] = lo; phi[wid][w] = hi; }
    }
    __syncthreads();

    // ---- Fold stage B: combine 8 warp partials; bin tid for tid<128 ----
    if (tid < 128) {
        int w = tid >> 2, k = tid & 3;
        int sh = (k >> 1) * 16;
        uint32_t cnt = 0;
#pragma unroll
        for (int q = 0; q < NWARPS; q++) {
            uint32_t p = (k & 1) ? phi[q][w] : plo[q][w];
            cnt += (p >> sh) & 0xFFFFu;                // total <= 8192
        }
        stats[tid] = (float)cnt * (1.0f / 8192.0f);    // f32(8192+1e-8)==8192
    }

    // ---- Remaining stats dims ----
    if (tid == 128) {
        double m = (double)s_sum / 8192.0;
        stats[128] = (float)m;                                                  // mean
        stats[129] = (float)sqrt(((double)s_ssq - (double)s_sum * m) / 8191.0); // unbiased std
    }
    if (tid >= 130 && tid < 138) stats[tid] = 0.0f;
    if (tid >= 138 && tid < 150) {
        uint32_t idx = (uint32_t)(b * 12 + (tid - 138));
        uint32_t bits = threefry_xor(0u, idx);
        stats[tid] = __uint_as_float((bits >> 9) | 0x3F800000u) - 1.0f;
    }
    __syncthreads();

    // ---- Layer 1: h = relu(stats @ W1 + b1); 1 column per thread ----
    {
        float acc = b1[tid];
#pragma unroll 10
        for (int s = 0; s < 150; s++)
            acc = fmaf(stats[s], W1[s * 256 + tid], acc);
        h[tid] = fmaxf(acc, 0.0f);
    }
    __syncthreads();

    // ---- Layer 2: out = h @ W2 + b2; first 128 threads ----
    if (tid < 128) {
        float o = b2[tid];
#pragma unroll 8
        for (int k = 0; k < 256; k++)
            o = fmaf(h[k], W2[k * 128 + tid], o);
        out[(size_t)b * 128 + tid] = o;
    }
}

extern "C" void kernel_launch(void* const* d_in, const int* in_sizes, int n_in,
                              void* d_out, int out_size) {
    const int*   tokens = (const int*)d_in[0];
    const float* W1     = (const float*)d_in[1];
    const float* b1     = (const float*)d_in[2];
    const float* W2     = (const float*)d_in[3];
    const float* b2     = (const float*)d_in[4];
    float* out = (float*)d_out;
    midi_stats_mlp_kernel<<<1024, NTHREADS>>>(tokens, W1, b1, W2, b2, out);
}

// round 11
// speedup vs baseline: 1.1308x; 1.1298x over previous
#include <cuda_runtime.h>
#include <cstdint>

#define T_LEN 8192
#define NT1 256
#define NWARPS 8
#define STATS_PAD 152          // 150 used, padded to multiple of 4
#define ROWS_PER_BLK 8         // kernel 2 row tile

__device__ float g_stats[1024 * STATS_PAD];

__device__ __forceinline__ uint32_t rotl32(uint32_t x, int r) {
    return (x << r) | (x >> (32 - r));
}

// Threefry-2x32, 20 rounds, key (0,42); x0^x1 fold (JAX partitionable path).
__device__ __forceinline__ uint32_t threefry_xor(uint32_t c0, uint32_t c1) {
    const uint32_t ks0 = 0u, ks1 = 42u;
    const uint32_t ks2 = ks0 ^ ks1 ^ 0x1BD11BDAu;
    uint32_t x0 = c0 + ks0, x1 = c1 + ks1;
#define TF_R4(a,b,c,d) \
    x0 += x1; x1 = rotl32(x1,a); x1 ^= x0; \
    x0 += x1; x1 = rotl32(x1,b); x1 ^= x0; \
    x0 += x1; x1 = rotl32(x1,c); x1 ^= x0; \
    x0 += x1; x1 = rotl32(x1,d); x1 ^= x0;
    TF_R4(13,15,26,6);   x0 += ks1; x1 += ks2 + 1u;
    TF_R4(17,29,16,24);  x0 += ks2; x1 += ks0 + 2u;
    TF_R4(13,15,26,6);   x0 += ks0; x1 += ks1 + 3u;
    TF_R4(17,29,16,24);  x0 += ks1; x1 += ks2 + 4u;
    TF_R4(13,15,26,6);   x0 += ks2; x1 += ks0 + 5u;
#undef TF_R4
    return x0 ^ x1;
}

// ============================ Kernel 1: stats ============================
__global__ __launch_bounds__(NT1)
void stats_kernel(const int* __restrict__ tokens) {
    // Per-THREAD private byte histograms; bank = lane, conflict-free, no atomics.
    __shared__ uint32_t priv[32 * NT1];             // 32 KB
    __shared__ uint32_t plo[NWARPS][32], phi[NWARPS][32];
    __shared__ unsigned s_sum, s_ssq;
    __shared__ float stats[STATS_PAD];

    const int b   = blockIdx.x;
    const int tid = threadIdx.x;
    const int wid = tid >> 5;
    const uint32_t lane = tid & 31u;

#pragma unroll
    for (int w = 0; w < 32; w++) priv[w * NT1 + tid] = 0u;
    if (tid == 0) { s_sum = 0u; s_ssq = 0u; }
    __syncthreads();

    // ---- hot loop: 32 tokens/thread, byte-RMW histogram + integer moments ----
    const int4* tp = reinterpret_cast<const int4*>(tokens + (size_t)b * T_LEN) + tid;
    unsigned char* mybase = reinterpret_cast<unsigned char*>(priv) + tid * 4;
    unsigned lsum = 0, lssq = 0;
#pragma unroll
    for (int i = 0; i < T_LEN / 4 / NT1; i++) {      // 8 iterations
        int4 v = tp[i * NT1];
        lsum += (unsigned)(v.x + v.y) + (unsigned)(v.z + v.w);
        lssq += (unsigned)(v.x * v.x) + (unsigned)(v.y * v.y)
              + (unsigned)(v.z * v.z) + (unsigned)(v.w * v.w);
        // byte offset for bin bn: word (bn>>2)*NT1 + tid, byte bn&3
        mybase[(((unsigned)v.x & 124u) << 8) + ((unsigned)v.x & 3u)]++;
        mybase[(((unsigned)v.y & 124u) << 8) + ((unsigned)v.y & 3u)]++;
        mybase[(((unsigned)v.z & 124u) << 8) + ((unsigned)v.z & 3u)]++;
        mybase[(((unsigned)v.w & 124u) << 8) + ((unsigned)v.w & 3u)]++;
    }
    lsum = __reduce_add_sync(0xffffffffu, lsum);
    lssq = __reduce_add_sync(0xffffffffu, lssq);
    if (lane == 0) { atomicAdd(&s_sum, lsum); atomicAdd(&s_ssq, lssq); }
    __syncthreads();

    // ---- fold A: per-warp SIMD-in-word sums (u16 fields <= 1024) ----
#pragma unroll 8
    for (int w = 0; w < 32; w++) {
        uint32_t x  = priv[w * NT1 + tid];
        uint32_t lo = __reduce_add_sync(0xffffffffu, x & 0x00FF00FFu);
        uint32_t hi = __reduce_add_sync(0xffffffffu, (x >> 8) & 0x00FF00FFu);
        if (lane == 0) { plo[wid][w] = lo; phi[wid][w] = hi; }
    }
    __syncthreads();

    // ---- fold B + remaining dims ----
    if (tid < 128) {
        int w = tid >> 2, k = tid & 3;
        int sh = (k >> 1) * 16;
        uint32_t cnt = 0;
#pragma unroll
        for (int q = 0; q < NWARPS; q++) {
            uint32_t p = (k & 1) ? phi[q][w] : plo[q][w];
            cnt += (p >> sh) & 0xFFFFu;
        }
        stats[tid] = (float)cnt * (1.0f / 8192.0f);   // f32(8192+1e-8)==8192
    }
    if (tid == 128) {
        double m = (double)s_sum / 8192.0;
        stats[128] = (float)m;
        stats[129] = (float)sqrt(((double)s_ssq - (double)s_sum * m) / 8191.0);
    }
    if (tid >= 130 && tid < 138) stats[tid] = 0.0f;
    if (tid >= 138 && tid < 150) {
        uint32_t idx = (uint32_t)(b * 12 + (tid - 138));
        uint32_t bits = threefry_xor(0u, idx);
        stats[tid] = __uint_as_float((bits >> 9) | 0x3F800000u) - 1.0f;
    }
    if (tid >= 150 && tid < STATS_PAD) stats[tid] = 0.0f;
    __syncthreads();

    if (tid < STATS_PAD) g_stats[b * STATS_PAD + tid] = stats[tid];
}

// ============================ Kernel 2: MLP ============================
// 8 rows per block; W1/W2 traffic amortized 8x; register-blocked accumulators.
__global__ __launch_bounds__(256)
void mlp_kernel(const float* __restrict__ W1,
                const float* __restrict__ b1,
                const float* __restrict__ W2,
                const float* __restrict__ b2,
                float* __restrict__ out) {
    __shared__ float st[STATS_PAD * ROWS_PER_BLK];   // stats transposed [s][r]
    __shared__ float ht[256 * ROWS_PER_BLK];         // hidden transposed [k][r]

    const int tid = threadIdx.x;
    const int b0  = blockIdx.x * ROWS_PER_BLK;

    // Load 8 rows of stats, transpose into st[s*8 + r]
    for (int i = tid; i < STATS_PAD * ROWS_PER_BLK; i += 256) {
        int r = i / STATS_PAD, s = i - r * STATS_PAD;
        st[s * ROWS_PER_BLK + r] = g_stats[(b0 + r) * STATS_PAD + s];
    }
    __syncthreads();

    // ---- Layer 1: col = tid; 8 row-accumulators per thread ----
    {
        float acc[ROWS_PER_BLK];
        float bias = b1[tid];
#pragma unroll
        for (int r = 0; r < ROWS_PER_BLK; r++) acc[r] = bias;
        const float4* st4 = reinterpret_cast<const float4*>(st);
#pragma unroll 5
        for (int s = 0; s < 150; s++) {
            float w = W1[s * 256 + tid];             // 1 LDG per s (L1/L2 hit)
            float4 v0 = st4[s * 2];                  // rows 0..3
            float4 v1 = st4[s * 2 + 1];              // rows 4..7
            acc[0] = fmaf(v0.x, w, acc[0]);
            acc[1] = fmaf(v0.y, w, acc[1]);
            acc[2] = fmaf(v0.z, w, acc[2]);
            acc[3] = fmaf(v0.w, w, acc[3]);
            acc[4] = fmaf(v1.x, w, acc[4]);
            acc[5] = fmaf(v1.y, w, acc[5]);
            acc[6] = fmaf(v1.z, w, acc[6]);
            acc[7] = fmaf(v1.w, w, acc[7]);
        }
        float4* ht4 = reinterpret_cast<float4*>(ht);
        float4 o0 = make_float4(fmaxf(acc[0],0.f), fmaxf(acc[1],0.f),
                                fmaxf(acc[2],0.f), fmaxf(acc[3],0.f));
        float4 o1 = make_float4(fmaxf(acc[4],0.f), fmaxf(acc[5],0.f),
                                fmaxf(acc[6],0.f), fmaxf(acc[7],0.f));
        ht4[tid * 2]     = o0;                        // ht[k=tid][0..3]
        ht4[tid * 2 + 1] = o1;                        // ht[k=tid][4..7]
    }
    __syncthreads();

    // ---- Layer 2: 256 threads = 128 cols x 2 row-halves; 4 rows/thread ----
    {
        const int col  = tid & 127;
        const int half = tid >> 7;                    // 0: rows 0-3, 1: rows 4-7
        float acc[4];
        float bias = b2[col];
#pragma unroll
        for (int j = 0; j < 4; j++) acc[j] = bias;
        const float4* ht4 = reinterpret_cast<const float4*>(ht);
#pragma unroll 8
        for (int k = 0; k < 256; k++) {
            float w = W2[k * 128 + col];              // 1 LDG per k
            float4 hv = ht4[k * 2 + half];            // broadcast LDS.128
            acc[0] = fmaf(hv.x, w, acc[0]);
            acc[1] = fmaf(hv.y, w, acc[1]);
            acc[2] = fmaf(hv.z, w, acc[2]);
            acc[3] = fmaf(hv.w, w, acc[3]);
        }
#pragma unroll
        for (int j = 0; j < 4; j++) {
            int r = half * 4 + j;
            out[(size_t)(b0 + r) * 128 + col] = acc[j];
        }
    }
}

extern "C" void kernel_launch(void* const* d_in, const int* in_sizes, int n_in,
                              void* d_out, int out_size) {
    const int*   tokens = (const int*)d_in[0];
    const float* W1     = (const float*)d_in[1];
    const float* b1     = (const float*)d_in[2];
    const float* W2     = (const float*)d_in[3];
    const float* b2     = (const float*)d_in[4];
    float* out = (float*)d_out;
    stats_kernel<<<1024, NT1>>>(tokens);
    mlp_kernel<<<1024 / ROWS_PER_BLK, 256>>>(W1, b1, W2, b2, out);
}

// round 12
// speedup vs baseline: 1.2049x; 1.0656x over previous
#include <cuda_runtime.h>
#include <cstdint>

#define T_LEN 8192
#define NROWS 8               // rows per block
#define NTHREADS 512          // 16 warps
#define TPR 64                // threads per row
#define STP 152               // padded stats dim

__device__ __forceinline__ uint32_t rotl32(uint32_t x, int r) {
    return (x << r) | (x >> (32 - r));
}

// Threefry-2x32, 20 rounds, key (0,42); x0^x1 fold (JAX partitionable path).
__device__ __forceinline__ uint32_t threefry_xor(uint32_t c0, uint32_t c1) {
    const uint32_t ks0 = 0u, ks1 = 42u;
    const uint32_t ks2 = ks0 ^ ks1 ^ 0x1BD11BDAu;
    uint32_t x0 = c0 + ks0, x1 = c1 + ks1;
#define TF_R4(a,b,c,d) \
    x0 += x1; x1 = rotl32(x1,a); x1 ^= x0; \
    x0 += x1; x1 = rotl32(x1,b); x1 ^= x0; \
    x0 += x1; x1 = rotl32(x1,c); x1 ^= x0; \
    x0 += x1; x1 = rotl32(x1,d); x1 ^= x0;
    TF_R4(13,15,26,6);   x0 += ks1; x1 += ks2 + 1u;
    TF_R4(17,29,16,24);  x0 += ks2; x1 += ks0 + 2u;
    TF_R4(13,15,26,6);   x0 += ks0; x1 += ks1 + 3u;
    TF_R4(17,29,16,24);  x0 += ks1; x1 += ks2 + 4u;
    TF_R4(13,15,26,6);   x0 += ks2; x1 += ks0 + 5u;
#undef TF_R4
    return x0 ^ x1;
}

__global__ __launch_bounds__(NTHREADS)
void fused_kernel(const int* __restrict__ tokens,
                  const float* __restrict__ W1,
                  const float* __restrict__ b1,
                  const float* __restrict__ W2,
                  const float* __restrict__ b2,
                  float* __restrict__ out) {
    // dynamic: per-thread private byte histograms, 32 words x 512 threads = 64KB
    extern __shared__ uint32_t priv[];
    // static (~33.5KB)
    __shared__ uint32_t plo[16][32], phi[16][32];
    __shared__ float st[STP * NROWS];        // stats transposed [s][r]
    __shared__ float ht[256 * NROWS];        // hidden transposed [k][r]
    __shared__ float red[512 * NROWS];       // partial-reduce scratch (16KB, reused)
    __shared__ unsigned s_sum[NROWS], s_ssq[NROWS];

    const int tid  = threadIdx.x;
    const int wid  = tid >> 5;
    const uint32_t lane = tid & 31u;
    const int b0   = blockIdx.x * NROWS;
    const int row  = tid >> 6;               // local row (8 rows, 64 thr each)
    const int rt   = tid & 63;               // thread-in-row

#pragma unroll
    for (int w = 0; w < 32; w++) priv[w * NTHREADS + tid] = 0u;
    if (tid < NROWS) { s_sum[tid] = 0u; s_ssq[tid] = 0u; }
    __syncthreads();

    // ---- Histogram + moments: 128 tokens/thread, front-batched int4 ----
    const int4* tp = reinterpret_cast<const int4*>(tokens + (size_t)(b0 + row) * T_LEN) + rt;
    unsigned char* mybase = reinterpret_cast<unsigned char*>(priv) + tid * 4;
    unsigned lsum = 0, lssq = 0;
#pragma unroll
    for (int bb = 0; bb < 4; bb++) {
        int4 v[8];
#pragma unroll
        for (int j = 0; j < 8; j++) v[j] = tp[(bb * 8 + j) * TPR];
#pragma unroll
        for (int j = 0; j < 8; j++) {
            int4 t = v[j];
            lsum += (unsigned)(t.x + t.y) + (unsigned)(t.z + t.w);
            lssq += (unsigned)(t.x * t.x) + (unsigned)(t.y * t.y)
                  + (unsigned)(t.z * t.z) + (unsigned)(t.w * t.w);
            // bin b -> byte: tid*4 + ((b&124)<<9) + (b&3)  [word (b>>2)*512 + tid]
            mybase[(((unsigned)t.x & 124u) << 9) + ((unsigned)t.x & 3u)]++;
            mybase[(((unsigned)t.y & 124u) << 9) + ((unsigned)t.y & 3u)]++;
            mybase[(((unsigned)t.z & 124u) << 9) + ((unsigned)t.z & 3u)]++;
            mybase[(((unsigned)t.w & 124u) << 9) + ((unsigned)t.w & 3u)]++;
        }
    }
    lsum = __reduce_add_sync(0xffffffffu, lsum);
    lssq = __reduce_add_sync(0xffffffffu, lssq);
    if (lane == 0) { atomicAdd(&s_sum[row], lsum); atomicAdd(&s_ssq[row], lssq); }

    // ---- Fold A: per-warp SIMD-in-word sums (u16 fields <= 32*128 = 4096) ----
#pragma unroll 8
    for (int w = 0; w < 32; w++) {
        uint32_t x  = priv[w * NTHREADS + tid];       // bank = lane, CF
        uint32_t lo = __reduce_add_sync(0xffffffffu, x & 0x00FF00FFu);
        uint32_t hi = __reduce_add_sync(0xffffffffu, (x >> 8) & 0x00FF00FFu);
        if (lane == 0) { plo[wid][w] = lo; phi[wid][w] = hi; }
    }
    __syncthreads();

    // ---- Fold B: row r lives in warps 2r, 2r+1; 2 bins per thread ----
    {
        int r = tid >> 6;
        int bbase = tid & 63;
#pragma unroll
        for (int half = 0; half < 2; half++) {
            int bin = bbase + half * 64;
            int w = bin >> 2, k = bin & 3;
            int sh = (k >> 1) * 16;
            uint32_t p0 = (k & 1) ? phi[2 * r][w]     : plo[2 * r][w];
            uint32_t p1 = (k & 1) ? phi[2 * r + 1][w] : plo[2 * r + 1][w];
            uint32_t cnt = ((p0 >> sh) & 0xFFFFu) + ((p1 >> sh) & 0xFFFFu);
            st[bin * NROWS + r] = (float)cnt * (1.0f / 8192.0f);  // f32(8192+1e-8)==8192
        }
    }

    // ---- Remaining stats dims (transposed layout st[s*8 + r]) ----
    if (tid < NROWS) {
        int r = tid;
        double m = (double)s_sum[r] / 8192.0;
        st[128 * NROWS + r] = (float)m;
        st[129 * NROWS + r] =
            (float)sqrt(((double)s_ssq[r] - (double)s_sum[r] * m) / 8191.0);
    }
    if (tid >= 8 && tid < 72) {            // rhythm zeros: dims 130..137
        int t2 = tid - 8;
        st[(130 + (t2 >> 3)) * NROWS + (t2 & 7)] = 0.0f;
    }
    if (tid >= 72 && tid < 168) {          // harmony dims 138..149
        int t3 = tid - 72;
        int r = t3 / 12, j = t3 - r * 12;
        uint32_t idx = (uint32_t)((b0 + r) * 12 + j);
        uint32_t bits = threefry_xor(0u, idx);
        st[(138 + j) * NROWS + r] = __uint_as_float((bits >> 9) | 0x3F800000u) - 1.0f;
    }
    if (tid >= 168 && tid < 184) {         // pad dims 150,151
        int t4 = tid - 168;
        st[(150 + (t4 >> 3)) * NROWS + (t4 & 7)] = 0.0f;
    }
    __syncthreads();

    // ---- Layer 1: 256 cols x 2 s-chunks; 8 row-accs per thread ----
    {
        const int col  = tid & 255;
        const int half = tid >> 8;          // s in [half*75, half*75+75)
        float acc[NROWS];
#pragma unroll
        for (int r = 0; r < NROWS; r++) acc[r] = 0.0f;
        const float4* st4 = reinterpret_cast<const float4*>(st);
        const int s0 = half * 75;
#pragma unroll 5
        for (int s = s0; s < s0 + 75; s++) {
            float wv = W1[s * 256 + col];
            float4 v0 = st4[s * 2];         // rows 0..3 (broadcast)
            float4 v1 = st4[s * 2 + 1];     // rows 4..7
            acc[0] = fmaf(v0.x, wv, acc[0]);
            acc[1] = fmaf(v0.y, wv, acc[1]);
            acc[2] = fmaf(v0.z, wv, acc[2]);
            acc[3] = fmaf(v0.w, wv, acc[3]);
            acc[4] = fmaf(v1.x, wv, acc[4]);
            acc[5] = fmaf(v1.y, wv, acc[5]);
            acc[6] = fmaf(v1.z, wv, acc[6]);
            acc[7] = fmaf(v1.w, wv, acc[7]);
        }
        float4* red4 = reinterpret_cast<float4*>(red);
        red4[(half * 256 + col) * 2]     = make_float4(acc[0], acc[1], acc[2], acc[3]);
        red4[(half * 256 + col) * 2 + 1] = make_float4(acc[4], acc[5], acc[6], acc[7]);
    }
    __syncthreads();
    // reduce halves + bias + relu -> ht[col*8 + r]
    {
        const int col = tid & 255;
        const int rh  = tid >> 8;           // row-quad 0: r0-3, 1: r4-7
        const float4* red4 = reinterpret_cast<const float4*>(red);
        float4 a = red4[col * 2 + rh];
        float4 c = red4[(256 + col) * 2 + rh];
        float bias = b1[col];
        float4 o;
        o.x = fmaxf(a.x + c.x + bias, 0.0f);
        o.y = fmaxf(a.y + c.y + bias, 0.0f);
        o.z = fmaxf(a.z + c.z + bias, 0.0f);
        o.w = fmaxf(a.w + c.w + bias, 0.0f);
        reinterpret_cast<float4*>(ht)[col * 2 + rh] = o;
    }
    __syncthreads();

    // ---- Layer 2: 128 cols x 4 k-chunks; 8 row-accs per thread ----
    {
        const int col   = tid & 127;
        const int chunk = tid >> 7;         // k in [chunk*64, +64)
        float acc[NROWS];
#pragma unroll
        for (int r = 0; r < NROWS; r++) acc[r] = 0.0f;
        const float4* ht4 = reinterpret_cast<const float4*>(ht);
        const int k0 = chunk * 64;
#pragma unroll 8
        for (int k = k0; k < k0 + 64; k++) {
            float wv = W2[k * 128 + col];
            float4 h0 = ht4[k * 2];
            float4 h1 = ht4[k * 2 + 1];
            acc[0] = fmaf(h0.x, wv, acc[0]);
            acc[1] = fmaf(h0.y, wv, acc[1]);
            acc[2] = fmaf(h0.z, wv, acc[2]);
            acc[3] = fmaf(h0.w, wv, acc[3]);
            acc[4] = fmaf(h1.x, wv, acc[4]);
            acc[5] = fmaf(h1.y, wv, acc[5]);
            acc[6] = fmaf(h1.z, wv, acc[6]);
            acc[7] = fmaf(h1.w, wv, acc[7]);
        }
        float4* red4 = reinterpret_cast<float4*>(red);
        red4[(chunk * 128 + col) * 2]     = make_float4(acc[0], acc[1], acc[2], acc[3]);
        red4[(chunk * 128 + col) * 2 + 1] = make_float4(acc[4], acc[5], acc[6], acc[7]);
    }
    __syncthreads();
    // final reduce: 512 threads -> 1024 outputs (2 rows per thread)
    {
        const int col   = tid & 127;
        const int rpair = tid >> 7;         // rows 2*rpair, 2*rpair+1
        float bias = b2[col];
#pragma unroll
        for (int j = 0; j < 2; j++) {
            int r = rpair * 2 + j;
            float o = bias;
#pragma unroll
            for (int c = 0; c < 4; c++)
                o += red[(c * 128 + col) * 8 + r];
            out[(size_t)(b0 + r) * 128 + col] = o;
        }
    }
}

extern "C" void kernel_launch(void* const* d_in, const int* in_sizes, int n_in,
                              void* d_out, int out_size) {
    const int*   tokens = (const int*)d_in[0];
    const float* W1     = (const float*)d_in[1];
    const float* b1     = (const float*)d_in[2];
    const float* W2     = (const float*)d_in[3];
    const float* b2     = (const float*)d_in[4];
    float* out = (float*)d_out;
    cudaFuncSetAttribute(fused_kernel,
                         cudaFuncAttributeMaxDynamicSharedMemorySize, 65536);
    fused_kernel<<<128, NTHREADS, 65536>>>(tokens, W1, b1, W2, b2, out);
}

// round 14
// speedup vs baseline: 1.2797x; 1.0620x over previous
#include <cuda_runtime.h>
#include <cstdint>

#define T_LEN 8192
#define NROWS 8               // rows per block
#define NTHREADS 512          // 16 warps
#define TPR 64                // threads per row
#define STP 152               // padded stats dim

__device__ __forceinline__ uint32_t rotl32(uint32_t x, int r) {
    return (x << r) | (x >> (32 - r));
}

// Threefry-2x32, 20 rounds, key (0,42); x0^x1 fold (JAX partitionable path).
__device__ __forceinline__ uint32_t threefry_xor(uint32_t c0, uint32_t c1) {
    const uint32_t ks0 = 0u, ks1 = 42u;
    const uint32_t ks2 = ks0 ^ ks1 ^ 0x1BD11BDAu;
    uint32_t x0 = c0 + ks0, x1 = c1 + ks1;
#define TF_R4(a,b,c,d) \
    x0 += x1; x1 = rotl32(x1,a); x1 ^= x0; \
    x0 += x1; x1 = rotl32(x1,b); x1 ^= x0; \
    x0 += x1; x1 = rotl32(x1,c); x1 ^= x0; \
    x0 += x1; x1 = rotl32(x1,d); x1 ^= x0;
    TF_R4(13,15,26,6);   x0 += ks1; x1 += ks2 + 1u;
    TF_R4(17,29,16,24);  x0 += ks2; x1 += ks0 + 2u;
    TF_R4(13,15,26,6);   x0 += ks0; x1 += ks1 + 3u;
    TF_R4(17,29,16,24);  x0 += ks1; x1 += ks2 + 4u;
    TF_R4(13,15,26,6);   x0 += ks2; x1 += ks0 + 5u;
#undef TF_R4
    return x0 ^ x1;
}

// Process one batch of 8 int4: moments + conflict-free byte-RMW histogram.
__device__ __forceinline__ void proc_batch(const int4* v, unsigned char* mybase,
                                           unsigned& lsum, unsigned& lssq) {
#pragma unroll
    for (int j = 0; j < 8; j++) {
        int4 t = v[j];
        lsum += (unsigned)(t.x + t.y) + (unsigned)(t.z + t.w);
        lssq += (unsigned)(t.x * t.x) + (unsigned)(t.y * t.y)
              + (unsigned)(t.z * t.z) + (unsigned)(t.w * t.w);
        // bin b -> byte: tid*4 + ((b&124)<<9) + (b&3)   [word (b>>2)*512 + tid]
        mybase[(((unsigned)t.x & 124u) << 9) + ((unsigned)t.x & 3u)]++;
        mybase[(((unsigned)t.y & 124u) << 9) + ((unsigned)t.y & 3u)]++;
        mybase[(((unsigned)t.z & 124u) << 9) + ((unsigned)t.z & 3u)]++;
        mybase[(((unsigned)t.w & 124u) << 9) + ((unsigned)t.w & 3u)]++;
    }
}

__global__ __launch_bounds__(NTHREADS)
void fused_kernel(const int* __restrict__ tokens,
                  const float* __restrict__ W1,
                  const float* __restrict__ b1,
                  const float* __restrict__ W2,
                  const float* __restrict__ b2,
                  float* __restrict__ out) {
    // dynamic: per-thread private byte histograms, 32 words x 512 threads = 64KB
    extern __shared__ uint32_t priv[];
    // static (~33.5KB)
    __shared__ uint32_t plo[16][32], phi[16][32];
    __shared__ float st[STP * NROWS];        // stats transposed [s][r]
    __shared__ float ht[256 * NROWS];        // hidden transposed [k][r]
    __shared__ float red[512 * NROWS];       // partial-reduce scratch (16KB, reused)
    __shared__ unsigned s_sum[NROWS], s_ssq[NROWS];

    const int tid  = threadIdx.x;
    const int wid  = tid >> 5;
    const uint32_t lane = tid & 31u;
    const int b0   = blockIdx.x * NROWS;
    const int row  = tid >> 6;               // local row (8 rows, 64 thr each)
    const int rt   = tid & 63;               // thread-in-row

    // ---- Software-pipelined token stream: ALWAYS 8 int4 in flight ----
    const int4* tp = reinterpret_cast<const int4*>(tokens + (size_t)(b0 + row) * T_LEN) + rt;
    int4 va[8], vb[8];
#pragma unroll
    for (int j = 0; j < 8; j++) va[j] = tp[j * TPR];                 // batch 0

    // zero private histograms while batch0 is in flight
#pragma unroll
    for (int w = 0; w < 32; w++) priv[w * NTHREADS + tid] = 0u;
    if (tid < NROWS) { s_sum[tid] = 0u; s_ssq[tid] = 0u; }
    __syncthreads();

    unsigned char* mybase = reinterpret_cast<unsigned char*>(priv) + tid * 4;
    unsigned lsum = 0, lssq = 0;

#pragma unroll
    for (int j = 0; j < 8; j++) vb[j] = tp[(8 + j) * TPR];           // batch 1
    proc_batch(va, mybase, lsum, lssq);                              // proc 0
#pragma unroll
    for (int j = 0; j < 8; j++) va[j] = tp[(16 + j) * TPR];          // batch 2
    proc_batch(vb, mybase, lsum, lssq);                              // proc 1
#pragma unroll
    for (int j = 0; j < 8; j++) vb[j] = tp[(24 + j) * TPR];          // batch 3
    proc_batch(va, mybase, lsum, lssq);                              // proc 2
    proc_batch(vb, mybase, lsum, lssq);                              // proc 3

    lsum = __reduce_add_sync(0xffffffffu, lsum);
    lssq = __reduce_add_sync(0xffffffffu, lssq);
    if (lane == 0) { atomicAdd(&s_sum[row], lsum); atomicAdd(&s_ssq[row], lssq); }

    // ---- Fold A: per-warp SIMD-in-word sums (u16 fields <= 32*128 = 4096) ----
#pragma unroll 8
    for (int w = 0; w < 32; w++) {
        uint32_t x  = priv[w * NTHREADS + tid];       // bank = lane, CF
        uint32_t lo = __reduce_add_sync(0xffffffffu, x & 0x00FF00FFu);
        uint32_t hi = __reduce_add_sync(0xffffffffu, (x >> 8) & 0x00FF00FFu);
        if (lane == 0) { plo[wid][w] = lo; phi[wid][w] = hi; }
    }
    __syncthreads();

    // ---- Fold B: row r lives in warps 2r, 2r+1; 2 bins per thread ----
    {
        int r = tid >> 6;
        int bbase = tid & 63;
#pragma unroll
        for (int half = 0; half < 2; half++) {
            int bin = bbase + half * 64;
            int w = bin >> 2, k = bin & 3;
            int sh = (k >> 1) * 16;
            uint32_t p0 = (k & 1) ? phi[2 * r][w]     : plo[2 * r][w];
            uint32_t p1 = (k & 1) ? phi[2 * r + 1][w] : plo[2 * r + 1][w];
            uint32_t cnt = ((p0 >> sh) & 0xFFFFu) + ((p1 >> sh) & 0xFFFFu);
            st[bin * NROWS + r] = (float)cnt * (1.0f / 8192.0f);  // f32(8192+1e-8)==8192
        }
    }

    // ---- Remaining stats dims (transposed layout st[s*8 + r]) ----
    if (tid < NROWS) {
        int r = tid;
        double m = (double)s_sum[r] / 8192.0;
        st[128 * NROWS + r] = (float)m;
        st[129 * NROWS + r] =
            (float)sqrt(((double)s_ssq[r] - (double)s_sum[r] * m) / 8191.0);
    }
    if (tid >= 8 && tid < 72) {            // rhythm zeros: dims 130..137
        int t2 = tid - 8;
        st[(130 + (t2 >> 3)) * NROWS + (t2 & 7)] = 0.0f;
    }
    if (tid >= 72 && tid < 168) {          // harmony dims 138..149
        int t3 = tid - 72;
        int r = t3 / 12, j = t3 - r * 12;
        uint32_t idx = (uint32_t)((b0 + r) * 12 + j);
        uint32_t bits = threefry_xor(0u, idx);
        st[(138 + j) * NROWS + r] = __uint_as_float((bits >> 9) | 0x3F800000u) - 1.0f;
    }
    if (tid >= 168 && tid < 184) {         // pad dims 150,151
        int t4 = tid - 168;
        st[(150 + (t4 >> 3)) * NROWS + (t4 & 7)] = 0.0f;
    }
    __syncthreads();

    // ---- Layer 1: 256 cols x 2 s-chunks; 8 row-accs per thread ----
    {
        const int col  = tid & 255;
        const int half = tid >> 8;          // s in [half*75, half*75+75)
        float acc[NROWS];
#pragma unroll
        for (int r = 0; r < NROWS; r++) acc[r] = 0.0f;
        const float4* st4 = reinterpret_cast<const float4*>(st);
        const int s0 = half * 75;
#pragma unroll 5
        for (int s = s0; s < s0 + 75; s++) {
            float wv = W1[s * 256 + col];
            float4 v0 = st4[s * 2];         // rows 0..3 (broadcast)
            float4 v1 = st4[s * 2 + 1];     // rows 4..7
            acc[0] = fmaf(v0.x, wv, acc[0]);
            acc[1] = fmaf(v0.y, wv, acc[1]);
            acc[2] = fmaf(v0.z, wv, acc[2]);
            acc[3] = fmaf(v0.w, wv, acc[3]);
            acc[4] = fmaf(v1.x, wv, acc[4]);
            acc[5] = fmaf(v1.y, wv, acc[5]);
            acc[6] = fmaf(v1.z, wv, acc[6]);
            acc[7] = fmaf(v1.w, wv, acc[7]);
        }
        float4* red4 = reinterpret_cast<float4*>(red);
        red4[(half * 256 + col) * 2]     = make_float4(acc[0], acc[1], acc[2], acc[3]);
        red4[(half * 256 + col) * 2 + 1] = make_float4(acc[4], acc[5], acc[6], acc[7]);
    }
    __syncthreads();
    // reduce halves + bias + relu -> ht[col*8 + r]
    {
        const int col = tid & 255;
        const int rh  = tid >> 8;           // row-quad 0: r0-3, 1: r4-7
        const float4* red4 = reinterpret_cast<const float4*>(red);
        float4 a = red4[col * 2 + rh];
        float4 c = red4[(256 + col) * 2 + rh];
        float bias = b1[col];
        float4 o;
        o.x = fmaxf(a.x + c.x + bias, 0.0f);
        o.y = fmaxf(a.y + c.y + bias, 0.0f);
        o.z = fmaxf(a.z + c.z + bias, 0.0f);
        o.w = fmaxf(a.w + c.w + bias, 0.0f);
        reinterpret_cast<float4*>(ht)[col * 2 + rh] = o;
    }
    __syncthreads();

    // ---- Layer 2: 128 cols x 4 k-chunks; 8 row-accs per thread ----
    {
        const int col   = tid & 127;
        const int chunk = tid >> 7;         // k in [chunk*64, +64)
        float acc[NROWS];
#pragma unroll
        for (int r = 0; r < NROWS; r++) acc[r] = 0.0f;
        const float4* ht4 = reinterpret_cast<const float4*>(ht);
        const int k0 = chunk * 64;
#pragma unroll 8
        for (int k = k0; k < k0 + 64; k++) {
            float wv = W2[k * 128 + col];
            float4 h0 = ht4[k * 2];
            float4 h1 = ht4[k * 2 + 1];
            acc[0] = fmaf(h0.x, wv, acc[0]);
            acc[1] = fmaf(h0.y, wv, acc[1]);
            acc[2] = fmaf(h0.z, wv, acc[2]);
            acc[3] = fmaf(h0.w, wv, acc[3]);
            acc[4] = fmaf(h1.x, wv, acc[4]);
            acc[5] = fmaf(h1.y, wv, acc[5]);
            acc[6] = fmaf(h1.z, wv, acc[6]);
            acc[7] = fmaf(h1.w, wv, acc[7]);
        }
        float4* red4 = reinterpret_cast<float4*>(red);
        red4[(chunk * 128 + col) * 2]     = make_float4(acc[0], acc[1], acc[2], acc[3]);
        red4[(chunk * 128 + col) * 2 + 1] = make_float4(acc[4], acc[5], acc[6], acc[7]);
    }
    __syncthreads();
    // final reduce: 512 threads -> 1024 outputs (2 rows per thread)
    {
        const int col   = tid & 127;
        const int rpair = tid >> 7;         // rows 2*rpair, 2*rpair+1
        float bias = b2[col];
#pragma unroll
        for (int j = 0; j < 2; j++) {
            int r = rpair * 2 + j;
            float o = bias;
#pragma unroll
            for (int c = 0; c < 4; c++)
                o += red[(c * 128 + col) * 8 + r];
            out[(size_t)(b0 + r) * 128 + col] = o;
        }
    }
}

extern "C" void kernel_launch(void* const* d_in, const int* in_sizes, int n_in,
                              void* d_out, int out_size) {
    const int*   tokens = (const int*)d_in[0];
    const float* W1     = (const float*)d_in[1];
    const float* b1     = (const float*)d_in[2];
    const float* W2     = (const float*)d_in[3];
    const float* b2     = (const float*)d_in[4];
    float* out = (float*)d_out;
    cudaFuncSetAttribute(fused_kernel,
                         cudaFuncAttributeMaxDynamicSharedMemorySize, 65536);
    fused_kernel<<<128, NTHREADS, 65536>>>(tokens, W1, b1, W2, b2, out);
}

// round 16
// speedup vs baseline: 1.7738x; 1.3861x over previous
#include <cuda_runtime.h>
#include <cstdint>

#define T_LEN 8192
#define NROWS 8               // rows per block
#define NTHREADS 512          // 16 warps
#define TPR 64                // threads per row
#define STP 152               // padded stats dim

__device__ __forceinline__ uint32_t rotl32(uint32_t x, int r) {
    return (x << r) | (x >> (32 - r));
}

// Threefry-2x32, 20 rounds, key (0,42); x0^x1 fold (JAX partitionable path).
__device__ __forceinline__ uint32_t threefry_xor(uint32_t c0, uint32_t c1) {
    const uint32_t ks0 = 0u, ks1 = 42u;
    const uint32_t ks2 = ks0 ^ ks1 ^ 0x1BD11BDAu;
    uint32_t x0 = c0 + ks0, x1 = c1 + ks1;
#define TF_R4(a,b,c,d) \
    x0 += x1; x1 = rotl32(x1,a); x1 ^= x0; \
    x0 += x1; x1 = rotl32(x1,b); x1 ^= x0; \
    x0 += x1; x1 = rotl32(x1,c); x1 ^= x0; \
    x0 += x1; x1 = rotl32(x1,d); x1 ^= x0;
    TF_R4(13,15,26,6);   x0 += ks1; x1 += ks2 + 1u;
    TF_R4(17,29,16,24);  x0 += ks2; x1 += ks0 + 2u;
    TF_R4(13,15,26,6);   x0 += ks0; x1 += ks1 + 3u;
    TF_R4(17,29,16,24);  x0 += ks1; x1 += ks2 + 4u;
    TF_R4(13,15,26,6);   x0 += ks2; x1 += ks0 + 5u;
#undef TF_R4
    return x0 ^ x1;
}

// Process one batch of 8 int4: moments + conflict-free byte-RMW histogram.
__device__ __forceinline__ void proc_batch(const int4* v, unsigned char* mybase,
                                           unsigned& lsum, unsigned& lssq) {
#pragma unroll
    for (int j = 0; j < 8; j++) {
        int4 t = v[j];
        lsum += (unsigned)(t.x + t.y) + (unsigned)(t.z + t.w);
        lssq += (unsigned)(t.x * t.x) + (unsigned)(t.y * t.y)
              + (unsigned)(t.z * t.z) + (unsigned)(t.w * t.w);
        // bin b -> byte: tid*4 + ((b&124)<<9) + (b&3)   [word (b>>2)*512 + tid]
        mybase[(((unsigned)t.x & 124u) << 9) + ((unsigned)t.x & 3u)]++;
        mybase[(((unsigned)t.y & 124u) << 9) + ((unsigned)t.y & 3u)]++;
        mybase[(((unsigned)t.z & 124u) << 9) + ((unsigned)t.z & 3u)]++;
        mybase[(((unsigned)t.w & 124u) << 9) + ((unsigned)t.w & 3u)]++;
    }
}

__global__ __launch_bounds__(NTHREADS, 1)   // 1 blk/SM: unlock 128-reg budget
void fused_kernel(const int* __restrict__ tokens,
                  const float* __restrict__ W1,
                  const float* __restrict__ b1,
                  const float* __restrict__ W2,
                  const float* __restrict__ b2,
                  float* __restrict__ out) {
    // dynamic: per-thread private byte histograms, 32 words x 512 threads = 64KB
    extern __shared__ uint32_t priv[];
    // static (~33.5KB)
    __shared__ uint32_t plo[16][32], phi[16][32];
    __shared__ float st[STP * NROWS];        // stats transposed [s][r]
    __shared__ float ht[256 * NROWS];        // hidden transposed [k][r]
    __shared__ float red[512 * NROWS];       // partial-reduce scratch (16KB, reused)
    __shared__ unsigned s_sum[NROWS], s_ssq[NROWS];

    const int tid  = threadIdx.x;
    const int wid  = tid >> 5;
    const uint32_t lane = tid & 31u;
    const int b0   = blockIdx.x * NROWS;
    const int row  = tid >> 6;               // local row (8 rows, 64 thr each)
    const int rt   = tid & 63;               // thread-in-row

    // ---- Software-pipelined token stream: ALWAYS 8 int4 in flight ----
    const int4* tp = reinterpret_cast<const int4*>(tokens + (size_t)(b0 + row) * T_LEN) + rt;
    int4 va[8], vb[8];
#pragma unroll
    for (int j = 0; j < 8; j++) va[j] = tp[j * TPR];                 // batch 0

    // zero private histograms while batch0 is in flight
#pragma unroll
    for (int w = 0; w < 32; w++) priv[w * NTHREADS + tid] = 0u;
    if (tid < NROWS) { s_sum[tid] = 0u; s_ssq[tid] = 0u; }
    __syncthreads();

    unsigned char* mybase = reinterpret_cast<unsigned char*>(priv) + tid * 4;
    unsigned lsum = 0, lssq = 0;

#pragma unroll
    for (int j = 0; j < 8; j++) vb[j] = tp[(8 + j) * TPR];           // batch 1
    proc_batch(va, mybase, lsum, lssq);                              // proc 0
#pragma unroll
    for (int j = 0; j < 8; j++) va[j] = tp[(16 + j) * TPR];          // batch 2
    proc_batch(vb, mybase, lsum, lssq);                              // proc 1
#pragma unroll
    for (int j = 0; j < 8; j++) vb[j] = tp[(24 + j) * TPR];          // batch 3
    proc_batch(va, mybase, lsum, lssq);                              // proc 2
    proc_batch(vb, mybase, lsum, lssq);                              // proc 3

    lsum = __reduce_add_sync(0xffffffffu, lsum);
    lssq = __reduce_add_sync(0xffffffffu, lssq);
    if (lane == 0) { atomicAdd(&s_sum[row], lsum); atomicAdd(&s_ssq[row], lssq); }

    // ---- Fold A: per-warp SIMD-in-word sums (u16 fields <= 32*128 = 4096) ----
#pragma unroll 8
    for (int w = 0; w < 32; w++) {
        uint32_t x  = priv[w * NTHREADS + tid];       // bank = lane, CF
        uint32_t lo = __reduce_add_sync(0xffffffffu, x & 0x00FF00FFu);
        uint32_t hi = __reduce_add_sync(0xffffffffu, (x >> 8) & 0x00FF00FFu);
        if (lane == 0) { plo[wid][w] = lo; phi[wid][w] = hi; }
    }
    __syncthreads();

    // ---- Fold B: row r lives in warps 2r, 2r+1; 2 bins per thread ----
    {
        int r = tid >> 6;
        int bbase = tid & 63;
#pragma unroll
        for (int half = 0; half < 2; half++) {
            int bin = bbase + half * 64;
            int w = bin >> 2, k = bin & 3;
            int sh = (k >> 1) * 16;
            uint32_t p0 = (k & 1) ? phi[2 * r][w]     : plo[2 * r][w];
            uint32_t p1 = (k & 1) ? phi[2 * r + 1][w] : plo[2 * r + 1][w];
            uint32_t cnt = ((p0 >> sh) & 0xFFFFu) + ((p1 >> sh) & 0xFFFFu);
            st[bin * NROWS + r] = (float)cnt * (1.0f / 8192.0f);  // f32(8192+1e-8)==8192
        }
    }

    // ---- Remaining stats dims (transposed layout st[s*8 + r]) ----
    if (tid < NROWS) {
        int r = tid;
        double m = (double)s_sum[r] / 8192.0;
        st[128 * NROWS + r] = (float)m;
        st[129 * NROWS + r] =
            (float)sqrt(((double)s_ssq[r] - (double)s_sum[r] * m) / 8191.0);
    }
    if (tid >= 8 && tid < 72) {            // rhythm zeros: dims 130..137
        int t2 = tid - 8;
        st[(130 + (t2 >> 3)) * NROWS + (t2 & 7)] = 0.0f;
    }
    if (tid >= 72 && tid < 168) {          // harmony dims 138..149
        int t3 = tid - 72;
        int r = t3 / 12, j = t3 - r * 12;
        uint32_t idx = (uint32_t)((b0 + r) * 12 + j);
        uint32_t bits = threefry_xor(0u, idx);
        st[(138 + j) * NROWS + r] = __uint_as_float((bits >> 9) | 0x3F800000u) - 1.0f;
    }
    if (tid >= 168 && tid < 184) {         // pad dims 150,151
        int t4 = tid - 168;
        st[(150 + (t4 >> 3)) * NROWS + (t4 & 7)] = 0.0f;
    }
    __syncthreads();

    // ---- Layer 1: 256 cols x 2 s-chunks; 8 row-accs per thread ----
    {
        const int col  = tid & 255;
        const int half = tid >> 8;          // s in [half*75, half*75+75)
        float acc[NROWS];
#pragma unroll
        for (int r = 0; r < NROWS; r++) acc[r] = 0.0f;
        const float4* st4 = reinterpret_cast<const float4*>(st);
        const int s0 = half * 75;
#pragma unroll 5
        for (int s = s0; s < s0 + 75; s++) {
            float wv = W1[s * 256 + col];
            float4 v0 = st4[s * 2];         // rows 0..3 (broadcast)
            float4 v1 = st4[s * 2 + 1];     // rows 4..7
            acc[0] = fmaf(v0.x, wv, acc[0]);
            acc[1] = fmaf(v0.y, wv, acc[1]);
            acc[2] = fmaf(v0.z, wv, acc[2]);
            acc[3] = fmaf(v0.w, wv, acc[3]);
            acc[4] = fmaf(v1.x, wv, acc[4]);
            acc[5] = fmaf(v1.y, wv, acc[5]);
            acc[6] = fmaf(v1.z, wv, acc[6]);
            acc[7] = fmaf(v1.w, wv, acc[7]);
        }
        float4* red4 = reinterpret_cast<float4*>(red);
        red4[(half * 256 + col) * 2]     = make_float4(acc[0], acc[1], acc[2], acc[3]);
        red4[(half * 256 + col) * 2 + 1] = make_float4(acc[4], acc[5], acc[6], acc[7]);
    }
    __syncthreads();
    // reduce halves + bias + relu -> ht[col*8 + r]
    {
        const int col = tid & 255;
        const int rh  = tid >> 8;           // row-quad 0: r0-3, 1: r4-7
        const float4* red4 = reinterpret_cast<const float4*>(red);
        float4 a = red4[col * 2 + rh];
        float4 c = red4[(256 + col) * 2 + rh];
        float bias = b1[col];
        float4 o;
        o.x = fmaxf(a.x + c.x + bias, 0.0f);
        o.y = fmaxf(a.y + c.y + bias, 0.0f);
        o.z = fmaxf(a.z + c.z + bias, 0.0f);
        o.w = fmaxf(a.w + c.w + bias, 0.0f);
        reinterpret_cast<float4*>(ht)[col * 2 + rh] = o;
    }
    __syncthreads();

    // ---- Layer 2: 128 cols x 4 k-chunks; 8 row-accs per thread ----
    {
        const int col   = tid & 127;
        const int chunk = tid >> 7;         // k in [chunk*64, +64)
        float acc[NROWS];
#pragma unroll
        for (int r = 0; r < NROWS; r++) acc[r] = 0.0f;
        const float4* ht4 = reinterpret_cast<const float4*>(ht);
        const int k0 = chunk * 64;
#pragma unroll 8
        for (int k = k0; k < k0 + 64; k++) {
            float wv = W2[k * 128 + col];
            float4 h0 = ht4[k * 2];
            float4 h1 = ht4[k * 2 + 1];
            acc[0] = fmaf(h0.x, wv, acc[0]);
            acc[1] = fmaf(h0.y, wv, acc[1]);
            acc[2] = fmaf(h0.z, wv, acc[2]);
            acc[3] = fmaf(h0.w, wv, acc[3]);
            acc[4] = fmaf(h1.x, wv, acc[4]);
            acc[5] = fmaf(h1.y, wv, acc[5]);
            acc[6] = fmaf(h1.z, wv, acc[6]);
            acc[7] = fmaf(h1.w, wv, acc[7]);
        }
        float4* red4 = reinterpret_cast<float4*>(red);
        red4[(chunk * 128 + col) * 2]     = make_float4(acc[0], acc[1], acc[2], acc[3]);
        red4[(chunk * 128 + col) * 2 + 1] = make_float4(acc[4], acc[5], acc[6], acc[7]);
    }
    __syncthreads();
    // final reduce: 512 threads -> 1024 outputs (2 rows per thread)
    {
        const int col   = tid & 127;
        const int rpair = tid >> 7;         // rows 2*rpair, 2*rpair+1
        float bias = b2[col];
#pragma unroll
        for (int j = 0; j < 2; j++) {
            int r = rpair * 2 + j;
            float o = bias;
#pragma unroll
            for (int c = 0; c < 4; c++)
                o += red[(c * 128 + col) * 8 + r];
            out[(size_t)(b0 + r) * 128 + col] = o;
        }
    }
}

extern "C" void kernel_launch(void* const* d_in, const int* in_sizes, int n_in,
                              void* d_out, int out_size) {
    const int*   tokens = (const int*)d_in[0];
    const float* W1     = (const float*)d_in[1];
    const float* b1     = (const float*)d_in[2];
    const float* W2     = (const float*)d_in[3];
    const float* b2     = (const float*)d_in[4];
    float* out = (float*)d_out;
    cudaFuncSetAttribute(fused_kernel,
                         cudaFuncAttributeMaxDynamicSharedMemorySize, 65536);
    fused_kernel<<<128, NTHREADS, 65536>>>(tokens, W1, b1, W2, b2, out);
}